// round 7
// baseline (speedup 1.0000x reference)
#include <cuda_runtime.h>
#include <math.h>

#define MAXN 20000
#define MAXE 320000

// ---- scratch (static device globals; referenced ONLY from device code) ----
__device__ float g_x[4][MAXN * 64];   // x_all slices: h, out1, out2, out3
__device__ float g_q[MAXN * 64];
__device__ float g_k[MAXN * 192];     // [node][slice(3)][64]
__device__ float g_v[MAXN * 192];
__device__ int   g_cnt[MAXN];
__device__ int   g_cur[MAXN];
__device__ int   g_off[MAXN + 1];
__device__ float g_dinv[MAXN];
__device__ int   g_src[MAXE];

// ---------------- CSR build ----------------
__global__ void k_zero(int n) {
    int i = blockIdx.x * blockDim.x + threadIdx.x;
    if (i < n) g_cnt[i] = 0;
}

__global__ void k_hist(const int* __restrict__ ei, int E) {
    int e = blockIdx.x * blockDim.x + threadIdx.x;
    if (e < E) atomicAdd(&g_cnt[ei[E + e]], 1);
}

// single-block exclusive scan of g_cnt -> g_off (+ cursor copy, + dinv)
__global__ void k_scan(int n) {
    __shared__ int ssum[1024];
    int tid = threadIdx.x;
    int chunk = (n + 1023) >> 10;
    int beg = tid * chunk;
    int end = min(beg + chunk, n);
    int s = 0;
    for (int i = beg; i < end; i++) s += g_cnt[i];
    ssum[tid] = s;
    __syncthreads();
    for (int d = 1; d < 1024; d <<= 1) {
        int v = (tid >= d) ? ssum[tid - d] : 0;
        __syncthreads();
        ssum[tid] += v;
        __syncthreads();
    }
    int run = ssum[tid] - s;   // exclusive prefix
    for (int i = beg; i < end; i++) {
        g_off[i] = run;
        g_cur[i] = run;
        g_dinv[i] = rsqrtf((float)(g_cnt[i] + 1));  // +1 self-loop
        run += g_cnt[i];
    }
    if (tid == 1023) g_off[n] = ssum[1023];
}

__global__ void k_scatter(const int* __restrict__ ei, int E) {
    int e = blockIdx.x * blockDim.x + threadIdx.x;
    if (e < E) {
        int dst = ei[E + e];
        int p = atomicAdd(&g_cur[dst], 1);
        g_src[p] = ei[e];
    }
}

// ---------------- lin1: h = relu(x @ W1 + b1), 256 -> 64 ----------------
__global__ void k_lin1(const float* __restrict__ x, const float* __restrict__ W,
                       const float* __restrict__ b, int n) {
    __shared__ float xs[16][256];
    int tx = threadIdx.x & 63;     // output col
    int ty = threadIdx.x >> 6;     // 0..3
    int base = blockIdx.x * 16;
    // cooperative load of 16 input rows (float4)
    for (int i = threadIdx.x; i < 16 * 64; i += 256) {
        int r = i >> 6, c4 = i & 63;
        int node = base + r;
        float4 vv = (node < n) ? ((const float4*)(x + (size_t)node * 256))[c4]
                               : make_float4(0.f, 0.f, 0.f, 0.f);
        ((float4*)xs[r])[c4] = vv;
    }
    __syncthreads();
    float bias = b[tx];
    float acc[4] = {bias, bias, bias, bias};
    #pragma unroll 4
    for (int k = 0; k < 256; k++) {
        float wv = W[k * 64 + tx];         // L1-resident (64KB), broadcast across ty
        #pragma unroll
        for (int j = 0; j < 4; j++) acc[j] += xs[ty * 4 + j][k] * wv;
    }
    #pragma unroll
    for (int j = 0; j < 4; j++) {
        int node = base + ty * 4 + j;
        if (node < n) g_x[0][node * 64 + tx] = fmaxf(acc[j], 0.f);
    }
}

// ---------------- generic 64x64 GEMM: dst = g_x[in_slice] @ W + b ----------------
// dst_kind: 0 -> g_q (stride 64), 1 -> g_k + out_slice*64 (stride 192),
//           2 -> g_v + out_slice*64 (stride 192)
__global__ void k_gemm64(const float* __restrict__ W, const float* __restrict__ b,
                         int in_slice, int dst_kind, int out_slice, int n) {
    __shared__ float xs[64][64];
    int tx = threadIdx.x & 63;     // output col
    int ty = threadIdx.x >> 6;     // 0..3
    int base = blockIdx.x * 64;

    const float* in = g_x[in_slice];
    float* out;
    int ostride;
    if (dst_kind == 0)      { out = g_q;                   ostride = 64;  }
    else if (dst_kind == 1) { out = g_k + out_slice * 64;  ostride = 192; }
    else                    { out = g_v + out_slice * 64;  ostride = 192; }

    float w[64];
    #pragma unroll
    for (int k = 0; k < 64; k++) w[k] = W[k * 64 + tx];  // W column in regs
    for (int i = threadIdx.x; i < 64 * 16; i += 256) {   // 64 rows x 16 float4
        int r = i >> 4, c4 = i & 15;
        int node = base + r;
        float4 vv = (node < n) ? ((const float4*)(in + (size_t)node * 64))[c4]
                               : make_float4(0.f, 0.f, 0.f, 0.f);
        ((float4*)xs[r])[c4] = vv;
    }
    __syncthreads();
    float bias = b[tx];
    for (int j = ty; j < 64; j += 4) {
        int node = base + j;
        if (node >= n) break;
        float acc = bias;
        #pragma unroll
        for (int kq = 0; kq < 16; kq++) {
            float4 xv = ((const float4*)xs[j])[kq];   // broadcast LDS.128
            acc += xv.x * w[4*kq] + xv.y * w[4*kq+1] + xv.z * w[4*kq+2] + xv.w * w[4*kq+3];
        }
        out[(size_t)node * ostride + tx] = acc;
    }
}

// -------- edge attention + aggregation: warp per destination node --------
// lane owns dims (2*lane, 2*lane+1); head = lane/4 (8 heads x 8 dims).
// Writes relu(result) into g_x[T].
template <int T>
__global__ void k_gather(int n) {
    int gw = (blockIdx.x * blockDim.x + threadIdx.x) >> 5;
    int lane = threadIdx.x & 31;
    if (gw >= n) return;
    int dst = gw;
    const float inv_sqrt_d = 0.3535533905932738f;  // 1/sqrt(8)
    float2 q2 = ((const float2*)(g_q + (size_t)dst * 64))[lane];
    float did = g_dinv[dst];
    int e0 = g_off[dst], e1 = g_off[dst + 1];
    float2 acc = make_float2(0.f, 0.f);
    for (int e = e0; e <= e1; e++) {          // e == e1 -> self-loop edge
        int src = (e < e1) ? g_src[e] : dst;
        const float2* kp = (const float2*)(g_k + (size_t)src * 192);
        const float2* vp = (const float2*)(g_v + (size_t)src * 192);
        float2 kk[T], vv[T];
        #pragma unroll
        for (int s = 0; s < T; s++) { kk[s] = kp[s * 32 + lane]; vv[s] = vp[s * 32 + lane]; }
        float sc[T];
        float mx = -1e30f;
        #pragma unroll
        for (int s = 0; s < T; s++) {
            float p = q2.x * kk[s].x + q2.y * kk[s].y;
            p += __shfl_xor_sync(0xffffffffu, p, 1);
            p += __shfl_xor_sync(0xffffffffu, p, 2);   // head-group (4 lanes) dot
            sc[s] = p * inv_sqrt_d;
            mx = fmaxf(mx, sc[s]);
        }
        float sum = 0.f;
        #pragma unroll
        for (int s = 0; s < T; s++) { sc[s] = __expf(sc[s] - mx); sum += sc[s]; }
        float scale = g_dinv[src] / sum;      // norm_e = dinv[src]*dinv[dst]; dst part applied at end
        float2 m = make_float2(0.f, 0.f);
        #pragma unroll
        for (int s = 0; s < T; s++) { m.x += sc[s] * vv[s].x; m.y += sc[s] * vv[s].y; }
        acc.x += m.x * scale;
        acc.y += m.y * scale;
    }
    float2 o;
    o.x = fmaxf(acc.x * did, 0.f);
    o.y = fmaxf(acc.y * did, 0.f);
    ((float2*)(g_x[T] + (size_t)dst * 64))[lane] = o;
}

// ---------------- lin2 + log_softmax: warp per node, reads g_x[3] ----------------
__global__ void k_lin2_ls(const float* __restrict__ W, const float* __restrict__ b,
                          float* __restrict__ out, int n) {
    int gw = (blockIdx.x * blockDim.x + threadIdx.x) >> 5;
    int lane = threadIdx.x & 31;
    if (gw >= n) return;
    const float* hr = g_x[3] + (size_t)gw * 64;
    float2 acc = ((const float2*)b)[lane];
    #pragma unroll 8
    for (int k = 0; k < 64; k++) {
        float hk = hr[k];                              // uniform broadcast load
        float2 w2 = ((const float2*)(W + k * 64))[lane];
        acc.x += hk * w2.x;
        acc.y += hk * w2.y;
    }
    float m = fmaxf(acc.x, acc.y);
    #pragma unroll
    for (int o = 16; o > 0; o >>= 1) m = fmaxf(m, __shfl_xor_sync(0xffffffffu, m, o));
    float se = __expf(acc.x - m) + __expf(acc.y - m);
    #pragma unroll
    for (int o = 16; o > 0; o >>= 1) se += __shfl_xor_sync(0xffffffffu, se, o);
    float lse = m + logf(se);
    float2 r;
    r.x = acc.x - lse;
    r.y = acc.y - lse;
    ((float2*)(out + (size_t)gw * 64))[lane] = r;
}

// ---------------- host launcher (kernel launches ONLY) ----------------
extern "C" void kernel_launch(void* const* d_in, const int* in_sizes, int n_in,
                              void* d_out, int out_size) {
    const float* x  = (const float*)d_in[0];
    const int*   ei = (const int*)d_in[1];     // int32: JAX downgrades int64 without x64
    const float* w1 = (const float*)d_in[2];
    const float* b1 = (const float*)d_in[3];
    const float* wq = (const float*)d_in[4];
    const float* bq = (const float*)d_in[5];
    const float* wk = (const float*)d_in[6];
    const float* bk = (const float*)d_in[7];
    const float* wv = (const float*)d_in[8];
    const float* bv = (const float*)d_in[9];
    const float* w2 = (const float*)d_in[10];
    const float* b2 = (const float*)d_in[11];

    int n = in_sizes[0] / 256;   // IN_C = 256
    int E = in_sizes[1] / 2;

    // CSR by destination (+ degrees/dinv)
    k_zero<<<(n + 255) / 256, 256>>>(n);
    k_hist<<<(E + 255) / 256, 256>>>(ei, E);
    k_scan<<<1, 1024>>>(n);
    k_scatter<<<(E + 255) / 256, 256>>>(ei, E);

    // input projection -> g_x[0]
    k_lin1<<<(n + 15) / 16, 256>>>(x, w1, b1, n);

    int gB64 = (n + 63) / 64;
    int gWarp = (n * 32 + 255) / 256;
    for (int l = 0; l < 3; l++) {
        int t = l + 1;
        const float* Wq = wq + l * 4096; const float* Bq = bq + l * 64;
        const float* Wk = wk + l * 4096; const float* Bk = bk + l * 64;
        const float* Wv = wv + l * 4096; const float* Bv = bv + l * 64;
        // q from last slice
        k_gemm64<<<gB64, 256>>>(Wq, Bq, t - 1, 0, 0, n);
        // k, v for all slices
        for (int s = 0; s < t; s++) {
            k_gemm64<<<gB64, 256>>>(Wk, Bk, s, 1, s, n);
            k_gemm64<<<gB64, 256>>>(Wv, Bv, s, 2, s, n);
        }
        if (t == 1)      k_gather<1><<<gWarp, 256>>>(n);
        else if (t == 2) k_gather<2><<<gWarp, 256>>>(n);
        else             k_gather<3><<<gWarp, 256>>>(n);
    }

    k_lin2_ls<<<gWarp, 256>>>(w2, b2, (float*)d_out, n);
}